// round 11
// baseline (speedup 1.0000x reference)
#include <cuda_runtime.h>
#include <cuda_fp16.h>
#include <mma.h>
#include <cstdint>

using namespace nvcuda;

#define B_SZ 16
#define N_SZ 2048
#define HID  128

// static scratch (no allocation allowed)
__device__ __half g_adjh[(size_t)B_SZ * N_SZ * N_SZ];   // 128 MB fp16 adjacency
__device__ __half g_xh[(size_t)B_SZ * N_SZ * HID];      //   8 MB fp16 x
__device__ __half g_p[(size_t)B_SZ * N_SZ * HID];       //   8 MB fp16 projected feats
__device__ __half g_hh[(size_t)B_SZ * N_SZ * HID];      //   8 MB fp16 intermediate h
__device__ __half g_wh[3 * HID * HID];                  //  96 KB fp16 weights

// ---------------------------------------------------------------------------
__device__ __forceinline__ void cp_async16(void* smem, const void* gmem) {
    unsigned s = (unsigned)__cvta_generic_to_shared(smem);
    asm volatile("cp.async.cg.shared.global [%0], [%1], 16;\n" :: "r"(s), "l"(gmem));
}
__device__ __forceinline__ void cp_commit() {
    asm volatile("cp.async.commit_group;\n");
}
template<int N> __device__ __forceinline__ void cp_wait() {
    asm volatile("cp.async.wait_group %0;\n" :: "n"(N));
}

// ---------------------------------------------------------------------------
// conv: fp32 -> fp16, vectorized (x only; adjacency handled inside agg_conv)
// ---------------------------------------------------------------------------
__global__ __launch_bounds__(256) void conv_fp16(const float4* __restrict__ in,
                                                 __half2* __restrict__ out,
                                                 int n4)
{
    int i = blockIdx.x * blockDim.x + threadIdx.x;
    int stride = gridDim.x * blockDim.x;
    for (; i < n4; i += stride) {
        float4 v = in[i];
        out[2 * i + 0] = __floats2half2_rn(v.x, v.y);
        out[2 * i + 1] = __floats2half2_rn(v.z, v.w);
    }
}

__global__ __launch_bounds__(256) void conv_w(const float* __restrict__ W0,
                                              const float* __restrict__ W1,
                                              const float* __restrict__ W2,
                                              __half* __restrict__ out)
{
    int i = blockIdx.x * blockDim.x + threadIdx.x;           // 0 .. 3*16384-1
    const float* src = (i < 16384) ? W0 : (i < 32768) ? W1 : W2;
    int off = i & 16383;
    out[i] = __float2half_rn(src[off]);
}

// ---------------------------------------------------------------------------
// pw_half: p[r, :] = fp16( src[r, :] @ W )   fp16 wmma m16n16k16, K=128
// ---------------------------------------------------------------------------
#define PW_LD   136
#define SC_LD   132
#define PW_SMEM (2 * 128 * PW_LD * 2)       // 69632 B

__global__ __launch_bounds__(256, 2) void pw_half(const __half* __restrict__ src,
                                                  const __half* __restrict__ W,
                                                  __half* __restrict__ out)
{
    extern __shared__ char smraw[];
    __half* sA = (__half*)smraw;
    __half* sB = sA + 128 * PW_LD;
    float*  sC = (float*)smraw;

    const int tid  = threadIdx.x;
    const int warp = tid >> 5;
    const int wr   = warp >> 1;
    const int wc   = warp & 1;
    const size_t row0 = (size_t)blockIdx.x * 128;

    #pragma unroll
    for (int it = 0; it < 8; ++it) {
        int i = tid + it * 256;
        int r = i >> 4, c = i & 15;
        cp_async16(sA + r * PW_LD + c * 8, src + (row0 + r) * HID + c * 8);
    }
    #pragma unroll
    for (int it = 0; it < 8; ++it) {
        int i = tid + it * 256;
        int r = i >> 4, c = i & 15;
        cp_async16(sB + r * PW_LD + c * 8, W + r * HID + c * 8);
    }
    cp_commit();
    cp_wait<0>();
    __syncthreads();

    wmma::fragment<wmma::accumulator, 16, 16, 16, float> acc[2][4];
    #pragma unroll
    for (int i = 0; i < 2; i++)
        #pragma unroll
        for (int j = 0; j < 4; j++) wmma::fill_fragment(acc[i][j], 0.f);

    #pragma unroll
    for (int ks = 0; ks < 8; ++ks) {
        wmma::fragment<wmma::matrix_a, 16, 16, 16, __half, wmma::row_major> fa[2];
        wmma::fragment<wmma::matrix_b, 16, 16, 16, __half, wmma::row_major> fb[4];
        #pragma unroll
        for (int i = 0; i < 2; i++)
            wmma::load_matrix_sync(fa[i], sA + (wr * 32 + i * 16) * PW_LD + ks * 16, PW_LD);
        #pragma unroll
        for (int j = 0; j < 4; j++)
            wmma::load_matrix_sync(fb[j], sB + (ks * 16) * PW_LD + wc * 64 + j * 16, PW_LD);
        #pragma unroll
        for (int i = 0; i < 2; i++)
            #pragma unroll
            for (int j = 0; j < 4; j++)
                wmma::mma_sync(acc[i][j], fa[i], fb[j], acc[i][j]);
    }
    __syncthreads();

    #pragma unroll
    for (int i = 0; i < 2; i++)
        #pragma unroll
        for (int j = 0; j < 4; j++)
            wmma::store_matrix_sync(sC + (wr * 32 + i * 16) * SC_LD + wc * 64 + j * 16,
                                    acc[i][j], SC_LD, wmma::mem_row_major);
    __syncthreads();

    __half* ob = out + row0 * HID;
    #pragma unroll
    for (int i = tid; i < 128 * 64; i += 256) {
        int r = i >> 6, c2 = i & 63;
        float2 v = *(const float2*)(sC + r * SC_LD + c2 * 2);
        *((__half2*)(ob + (size_t)r * HID) + c2) = __floats2half2_rn(v.x, v.y);
    }
}

// ---------------------------------------------------------------------------
// agg_half (layers 1,2): C = adjh @ p, fp16 wmma, KC=64, 3-stage cp.async,
// fused +bias / LN / ReLU epilogue.
// ---------------------------------------------------------------------------
#define KC     64
#define A_LDH  72
#define B_LDH  136
#define A_STGB (128 * A_LDH * 2)            // 18432 B
#define B_STGB (KC * B_LDH * 2)             // 17408 B
#define OFF_B  (3 * A_STGB)                 // 55296
#define OFF_ST (OFF_B + 3 * B_STGB)         // 107520
#define AGG_SMEM (OFF_ST + 1024)            // 108544 B

__device__ __forceinline__ void agg_load_stage(char* smem, int stg,
                                               const __half* __restrict__ adjb,
                                               const __half* __restrict__ pb,
                                               int k0, int tid)
{
    char* sA = smem + stg * A_STGB;
    char* sB = smem + OFF_B + stg * B_STGB;
    #pragma unroll
    for (int it = 0; it < 4; ++it) {
        int i = tid + it * 256;
        int r = i >> 3, c = i & 7;
        cp_async16(sA + (r * A_LDH + c * 8) * 2,
                   adjb + (size_t)r * N_SZ + k0 + c * 8);
    }
    #pragma unroll
    for (int it = 0; it < 4; ++it) {
        int i = tid + it * 256;
        int r = i >> 4, c = i & 15;
        cp_async16(sB + (r * B_LDH + c * 8) * 2,
                   pb + (size_t)(k0 + r) * HID + c * 8);
    }
    cp_commit();
}

template<typename OutT>
__global__ __launch_bounds__(256, 2) void agg_half(const __half* __restrict__ adjh,
                                                   const __half* __restrict__ p,
                                                   const float* __restrict__ bias,
                                                   const float* __restrict__ gamma,
                                                   const float* __restrict__ beta,
                                                   OutT* __restrict__ out)
{
    extern __shared__ char smem[];
    float* sC  = (float*)smem;
    float* sMu = (float*)(smem + OFF_ST);
    float* sRs = sMu + 128;

    const int tid  = threadIdx.x;
    const int warp = tid >> 5;
    const int wr   = warp >> 1;
    const int wc   = warp & 1;
    const int b    = blockIdx.y;
    const int n0   = blockIdx.x * 128;

    const __half* adjb = adjh + ((size_t)b * N_SZ + n0) * N_SZ;
    const __half* pb   = p + (size_t)b * N_SZ * HID;

    wmma::fragment<wmma::accumulator, 16, 16, 16, float> acc[2][4];
    #pragma unroll
    for (int i = 0; i < 2; i++)
        #pragma unroll
        for (int j = 0; j < 4; j++) wmma::fill_fragment(acc[i][j], 0.f);

    agg_load_stage(smem, 0, adjb, pb, 0, tid);
    agg_load_stage(smem, 1, adjb, pb, KC, tid);

    const int NT = N_SZ / KC;   // 32
    for (int kt = 0; kt < NT; ++kt) {
        cp_wait<1>();
        __syncthreads();

        int nk = kt + 2;
        if (nk < NT) agg_load_stage(smem, nk % 3, adjb, pb, nk * KC, tid);
        else         cp_commit();

        const int stg = kt % 3;
        const __half* sA = (const __half*)(smem + stg * A_STGB);
        const __half* sB = (const __half*)(smem + OFF_B + stg * B_STGB);

        #pragma unroll
        for (int ks = 0; ks < KC / 16; ++ks) {
            wmma::fragment<wmma::matrix_a, 16, 16, 16, __half, wmma::row_major> fa[2];
            wmma::fragment<wmma::matrix_b, 16, 16, 16, __half, wmma::row_major> fb[4];
            #pragma unroll
            for (int i = 0; i < 2; i++)
                wmma::load_matrix_sync(fa[i], sA + (wr * 32 + i * 16) * A_LDH + ks * 16, A_LDH);
            #pragma unroll
            for (int j = 0; j < 4; j++)
                wmma::load_matrix_sync(fb[j], sB + (ks * 16) * B_LDH + wc * 64 + j * 16, B_LDH);
            #pragma unroll
            for (int i = 0; i < 2; i++)
                #pragma unroll
                for (int j = 0; j < 4; j++)
                    wmma::mma_sync(acc[i][j], fa[i], fb[j], acc[i][j]);
        }
    }
    __syncthreads();

    #pragma unroll
    for (int i = 0; i < 2; i++)
        #pragma unroll
        for (int j = 0; j < 4; j++)
            wmma::store_matrix_sync(sC + (wr * 32 + i * 16) * SC_LD + wc * 64 + j * 16,
                                    acc[i][j], SC_LD, wmma::mem_row_major);
    __syncthreads();

    {
        int r = tid >> 1, half = tid & 1;
        const float* rp = sC + r * SC_LD + half * 64;
        const float* bp = bias + half * 64;
        float s = 0.f, s2 = 0.f;
        #pragma unroll 8
        for (int c = 0; c < 64; c++) {
            float v = rp[c] + __ldg(&bp[c]);
            s  += v;
            s2 += v * v;
        }
        s  += __shfl_xor_sync(0xFFFFFFFF, s, 1);
        s2 += __shfl_xor_sync(0xFFFFFFFF, s2, 1);
        if (half == 0) {
            float mu  = s * (1.f / 128.f);
            float var = s2 * (1.f / 128.f) - mu * mu;
            sMu[r] = mu;
            sRs[r] = rsqrtf(var + 1e-5f);
        }
    }
    __syncthreads();

    OutT* ob = out + ((size_t)b * N_SZ + n0) * HID;
    #pragma unroll
    for (int i = tid; i < 128 * 128; i += 256) {
        int r = i >> 7, c = i & 127;
        float v = sC[r * SC_LD + c] + __ldg(&bias[c]);
        v = (v - sMu[r]) * sRs[r] * __ldg(&gamma[c]) + __ldg(&beta[c]);
        v = fmaxf(v, 0.f);
        if constexpr (sizeof(OutT) == 2)
            ob[(size_t)r * HID + c] = __float2half_rn(v);
        else
            ob[(size_t)r * HID + c] = v;
    }
}

// ---------------------------------------------------------------------------
// agg_conv (layer 0): reads FP32 adj via LDG into registers, converts to fp16
// (writing both smem A-tile and g_adjh for layers 1,2), then the same wmma
// mainloop + LN/ReLU. KC=64; 2 fp16 A stages; 3-stage cp.async for B.
// ---------------------------------------------------------------------------
#define C_OFF_B   (2 * A_STGB)              // 36864
#define C_OFF_ST  (C_OFF_B + 3 * B_STGB)    // 89088
#define CONV_SMEM (C_OFF_ST + 1024)         // 90112 B

__device__ __forceinline__ void conv_loadB(char* smem, int stg,
                                           const __half* __restrict__ pb,
                                           int k0, int tid)
{
    char* sB = smem + C_OFF_B + stg * B_STGB;
    #pragma unroll
    for (int it = 0; it < 4; ++it) {        // 1024 chunks: 64 rows x 16
        int i = tid + it * 256;
        int r = i >> 4, c = i & 15;
        cp_async16(sB + (r * B_LDH + c * 8) * 2,
                   pb + (size_t)(k0 + r) * HID + c * 8);
    }
    cp_commit();
}

// load 128x64 fp32 adj tile -> convert -> fp16 smem stage + fp16 gmem
__device__ __forceinline__ void conv_loadA(char* smem, int stg,
                                           const float* __restrict__ adjb,
                                           __half* __restrict__ adjhb,
                                           int k0, int tid)
{
    __half* sA = (__half*)(smem + stg * A_STGB);
    #pragma unroll
    for (int it = 0; it < 8; ++it) {        // 2048 chunks: 128 rows x 16 float4
        int i = tid + it * 256;
        int r = i >> 4, c = i & 15;
        float4 v = *(const float4*)(adjb + (size_t)r * N_SZ + k0 + c * 4);
        union { __half2 h[2]; uint2 u; } pk;
        pk.h[0] = __floats2half2_rn(v.x, v.y);
        pk.h[1] = __floats2half2_rn(v.z, v.w);
        *(uint2*)(sA + r * A_LDH + c * 4) = pk.u;
        *(uint2*)(adjhb + (size_t)r * N_SZ + k0 + c * 4) = pk.u;
    }
}

__global__ __launch_bounds__(256, 2) void agg_conv(const float* __restrict__ adj,
                                                   const __half* __restrict__ p,
                                                   const float* __restrict__ bias,
                                                   const float* __restrict__ gamma,
                                                   const float* __restrict__ beta,
                                                   __half* __restrict__ adjh_out,
                                                   __half* __restrict__ out)
{
    extern __shared__ char smem[];
    float* sC  = (float*)smem;
    float* sMu = (float*)(smem + C_OFF_ST);
    float* sRs = sMu + 128;

    const int tid  = threadIdx.x;
    const int warp = tid >> 5;
    const int wr   = warp >> 1;
    const int wc   = warp & 1;
    const int b    = blockIdx.y;
    const int n0   = blockIdx.x * 128;

    const float*  adjb  = adj + ((size_t)b * N_SZ + n0) * N_SZ;
    __half*       adjhb = adjh_out + ((size_t)b * N_SZ + n0) * N_SZ;
    const __half* pb    = p + (size_t)b * N_SZ * HID;

    wmma::fragment<wmma::accumulator, 16, 16, 16, float> acc[2][4];
    #pragma unroll
    for (int i = 0; i < 2; i++)
        #pragma unroll
        for (int j = 0; j < 4; j++) wmma::fill_fragment(acc[i][j], 0.f);

    // prologue
    conv_loadB(smem, 0, pb, 0, tid);
    conv_loadB(smem, 1, pb, KC, tid);
    conv_loadA(smem, 0, adjb, adjhb, 0, tid);

    const int NT = N_SZ / KC;   // 32
    for (int kt = 0; kt < NT; ++kt) {
        cp_wait<1>();
        __syncthreads();        // A16[kt%2] + B[kt%3] visible

        int nk = kt + 2;
        if (nk < NT) conv_loadB(smem, nk % 3, pb, nk * KC, tid);
        else         cp_commit();

        const __half* sA = (const __half*)(smem + (kt % 2) * A_STGB);
        const __half* sB = (const __half*)(smem + C_OFF_B + (kt % 3) * B_STGB);

        #pragma unroll
        for (int ks = 0; ks < KC / 16; ++ks) {
            wmma::fragment<wmma::matrix_a, 16, 16, 16, __half, wmma::row_major> fa[2];
            wmma::fragment<wmma::matrix_b, 16, 16, 16, __half, wmma::row_major> fb[4];
            #pragma unroll
            for (int i = 0; i < 2; i++)
                wmma::load_matrix_sync(fa[i], sA + (wr * 32 + i * 16) * A_LDH + ks * 16, A_LDH);
            #pragma unroll
            for (int j = 0; j < 4; j++)
                wmma::load_matrix_sync(fb[j], sB + (ks * 16) * B_LDH + wc * 64 + j * 16, B_LDH);
            #pragma unroll
            for (int i = 0; i < 2; i++)
                #pragma unroll
                for (int j = 0; j < 4; j++)
                    wmma::mma_sync(acc[i][j], fa[i], fb[j], acc[i][j]);
        }

        // after MMA issue: fetch + convert next A tile into the other stage
        if (kt + 1 < NT)
            conv_loadA(smem, (kt + 1) % 2, adjb, adjhb, (kt + 1) * KC, tid);
    }
    __syncthreads();

    #pragma unroll
    for (int i = 0; i < 2; i++)
        #pragma unroll
        for (int j = 0; j < 4; j++)
            wmma::store_matrix_sync(sC + (wr * 32 + i * 16) * SC_LD + wc * 64 + j * 16,
                                    acc[i][j], SC_LD, wmma::mem_row_major);
    __syncthreads();

    {
        int r = tid >> 1, half = tid & 1;
        const float* rp = sC + r * SC_LD + half * 64;
        const float* bp = bias + half * 64;
        float s = 0.f, s2 = 0.f;
        #pragma unroll 8
        for (int c = 0; c < 64; c++) {
            float v = rp[c] + __ldg(&bp[c]);
            s  += v;
            s2 += v * v;
        }
        s  += __shfl_xor_sync(0xFFFFFFFF, s, 1);
        s2 += __shfl_xor_sync(0xFFFFFFFF, s2, 1);
        if (half == 0) {
            float mu  = s * (1.f / 128.f);
            float var = s2 * (1.f / 128.f) - mu * mu;
            sMu[r] = mu;
            sRs[r] = rsqrtf(var + 1e-5f);
        }
    }
    __syncthreads();

    __half* ob = out + ((size_t)b * N_SZ + n0) * HID;
    #pragma unroll
    for (int i = tid; i < 128 * 128; i += 256) {
        int r = i >> 7, c = i & 127;
        float v = sC[r * SC_LD + c] + __ldg(&bias[c]);
        v = (v - sMu[r]) * sRs[r] * __ldg(&gamma[c]) + __ldg(&beta[c]);
        ob[(size_t)r * HID + c] = __float2half_rn(fmaxf(v, 0.f));
    }
}

// ---------------------------------------------------------------------------
extern "C" void kernel_launch(void* const* d_in, const int* in_sizes, int n_in,
                              void* d_out, int out_size)
{
    const float* x   = (const float*)d_in[0];
    const float* adj = (const float*)d_in[1];
    const float* W[3]  = {(const float*)d_in[2],  (const float*)d_in[6],  (const float*)d_in[10]};
    const float* bb[3] = {(const float*)d_in[3],  (const float*)d_in[7],  (const float*)d_in[11]};
    const float* gg[3] = {(const float*)d_in[4],  (const float*)d_in[8],  (const float*)d_in[12]};
    const float* be[3] = {(const float*)d_in[5],  (const float*)d_in[9],  (const float*)d_in[13]};
    float* out = (float*)d_out;

    cudaFuncSetAttribute(pw_half, cudaFuncAttributeMaxDynamicSharedMemorySize, PW_SMEM);
    cudaFuncSetAttribute(agg_half<__half>, cudaFuncAttributeMaxDynamicSharedMemorySize, AGG_SMEM);
    cudaFuncSetAttribute(agg_half<float>,  cudaFuncAttributeMaxDynamicSharedMemorySize, AGG_SMEM);
    cudaFuncSetAttribute(agg_conv, cudaFuncAttributeMaxDynamicSharedMemorySize, CONV_SMEM);

    __half *adjh, *xh, *pp, *hh, *wh;
    cudaGetSymbolAddress((void**)&adjh, g_adjh);
    cudaGetSymbolAddress((void**)&xh,   g_xh);
    cudaGetSymbolAddress((void**)&pp,   g_p);
    cudaGetSymbolAddress((void**)&hh,   g_hh);
    cudaGetSymbolAddress((void**)&wh,   g_wh);

    conv_fp16<<<1024, 256>>>((const float4*)x, (__half2*)xh, (B_SZ * N_SZ * HID) / 4);
    conv_w<<<192, 256>>>(W[0], W[1], W[2], wh);

    dim3 aggGrid(N_SZ / 128, B_SZ);   // (16, 16)

    // layer 0: projection then fused convert+agg (also emits fp16 adjacency)
    pw_half<<<(B_SZ * N_SZ) / 128, 256, PW_SMEM>>>(xh, wh, pp);
    agg_conv<<<aggGrid, 256, CONV_SMEM>>>(adj, pp, bb[0], gg[0], be[0], adjh, hh);
    // layer 1
    pw_half<<<(B_SZ * N_SZ) / 128, 256, PW_SMEM>>>(hh, wh + 1 * HID * HID, pp);
    agg_half<__half><<<aggGrid, 256, AGG_SMEM>>>(adjh, pp, bb[1], gg[1], be[1], hh);
    // layer 2
    pw_half<<<(B_SZ * N_SZ) / 128, 256, PW_SMEM>>>(hh, wh + 2 * HID * HID, pp);
    agg_half<float><<<aggGrid, 256, AGG_SMEM>>>(adjh, pp, bb[2], gg[2], be[2], out);
}

// round 12
// speedup vs baseline: 1.0431x; 1.0431x over previous
#include <cuda_runtime.h>
#include <cuda_fp16.h>
#include <mma.h>
#include <cstdint>

using namespace nvcuda;

#define B_SZ 16
#define N_SZ 2048
#define HID  128

// static scratch (no allocation allowed)
__device__ __half g_adjh[(size_t)B_SZ * N_SZ * N_SZ];   // 128 MB fp16 adjacency
__device__ __half g_xh[(size_t)B_SZ * N_SZ * HID];      //   8 MB fp16 x
__device__ __half g_p[(size_t)B_SZ * N_SZ * HID];       //   8 MB fp16 projected feats
__device__ __half g_hh[(size_t)B_SZ * N_SZ * HID];      //   8 MB fp16 intermediate h
__device__ __half g_wh[3 * HID * HID];                  //  96 KB fp16 weights

// ---------------------------------------------------------------------------
__device__ __forceinline__ void cp_async16(void* smem, const void* gmem) {
    unsigned s = (unsigned)__cvta_generic_to_shared(smem);
    asm volatile("cp.async.cg.shared.global [%0], [%1], 16;\n" :: "r"(s), "l"(gmem));
}
__device__ __forceinline__ void cp_commit() {
    asm volatile("cp.async.commit_group;\n");
}
template<int N> __device__ __forceinline__ void cp_wait() {
    asm volatile("cp.async.wait_group %0;\n" :: "n"(N));
}

// ---------------------------------------------------------------------------
// conv: fp32 -> fp16, vectorized (x only; adjacency handled inside agg_conv)
// ---------------------------------------------------------------------------
__global__ __launch_bounds__(256) void conv_fp16(const float4* __restrict__ in,
                                                 __half2* __restrict__ out,
                                                 int n4)
{
    int i = blockIdx.x * blockDim.x + threadIdx.x;
    int stride = gridDim.x * blockDim.x;
    for (; i < n4; i += stride) {
        float4 v = in[i];
        out[2 * i + 0] = __floats2half2_rn(v.x, v.y);
        out[2 * i + 1] = __floats2half2_rn(v.z, v.w);
    }
}

__global__ __launch_bounds__(256) void conv_w(const float* __restrict__ W0,
                                              const float* __restrict__ W1,
                                              const float* __restrict__ W2,
                                              __half* __restrict__ out)
{
    int i = blockIdx.x * blockDim.x + threadIdx.x;           // 0 .. 3*16384-1
    const float* src = (i < 16384) ? W0 : (i < 32768) ? W1 : W2;
    int off = i & 16383;
    out[i] = __float2half_rn(src[off]);
}

// ---------------------------------------------------------------------------
// pw_half: p[r, :] = fp16( src[r, :] @ W )   fp16 wmma m16n16k16, K=128
// ---------------------------------------------------------------------------
#define PW_LD   136
#define SC_LD   132
#define PW_SMEM (2 * 128 * PW_LD * 2)       // 69632 B

__global__ __launch_bounds__(256, 2) void pw_half(const __half* __restrict__ src,
                                                  const __half* __restrict__ W,
                                                  __half* __restrict__ out)
{
    extern __shared__ char smraw[];
    __half* sA = (__half*)smraw;
    __half* sB = sA + 128 * PW_LD;
    float*  sC = (float*)smraw;

    const int tid  = threadIdx.x;
    const int warp = tid >> 5;
    const int wr   = warp >> 1;
    const int wc   = warp & 1;
    const size_t row0 = (size_t)blockIdx.x * 128;

    #pragma unroll
    for (int it = 0; it < 8; ++it) {
        int i = tid + it * 256;
        int r = i >> 4, c = i & 15;
        cp_async16(sA + r * PW_LD + c * 8, src + (row0 + r) * HID + c * 8);
    }
    #pragma unroll
    for (int it = 0; it < 8; ++it) {
        int i = tid + it * 256;
        int r = i >> 4, c = i & 15;
        cp_async16(sB + r * PW_LD + c * 8, W + r * HID + c * 8);
    }
    cp_commit();
    cp_wait<0>();
    __syncthreads();

    wmma::fragment<wmma::accumulator, 16, 16, 16, float> acc[2][4];
    #pragma unroll
    for (int i = 0; i < 2; i++)
        #pragma unroll
        for (int j = 0; j < 4; j++) wmma::fill_fragment(acc[i][j], 0.f);

    #pragma unroll
    for (int ks = 0; ks < 8; ++ks) {
        wmma::fragment<wmma::matrix_a, 16, 16, 16, __half, wmma::row_major> fa[2];
        wmma::fragment<wmma::matrix_b, 16, 16, 16, __half, wmma::row_major> fb[4];
        #pragma unroll
        for (int i = 0; i < 2; i++)
            wmma::load_matrix_sync(fa[i], sA + (wr * 32 + i * 16) * PW_LD + ks * 16, PW_LD);
        #pragma unroll
        for (int j = 0; j < 4; j++)
            wmma::load_matrix_sync(fb[j], sB + (ks * 16) * PW_LD + wc * 64 + j * 16, PW_LD);
        #pragma unroll
        for (int i = 0; i < 2; i++)
            #pragma unroll
            for (int j = 0; j < 4; j++)
                wmma::mma_sync(acc[i][j], fa[i], fb[j], acc[i][j]);
    }
    __syncthreads();

    #pragma unroll
    for (int i = 0; i < 2; i++)
        #pragma unroll
        for (int j = 0; j < 4; j++)
            wmma::store_matrix_sync(sC + (wr * 32 + i * 16) * SC_LD + wc * 64 + j * 16,
                                    acc[i][j], SC_LD, wmma::mem_row_major);
    __syncthreads();

    __half* ob = out + row0 * HID;
    #pragma unroll
    for (int i = tid; i < 128 * 64; i += 256) {
        int r = i >> 6, c2 = i & 63;
        float2 v = *(const float2*)(sC + r * SC_LD + c2 * 2);
        *((__half2*)(ob + (size_t)r * HID) + c2) = __floats2half2_rn(v.x, v.y);
    }
}

// ---------------------------------------------------------------------------
// agg_half (layers 1,2): C = adjh @ p, fp16 wmma, KC=64, 3-stage cp.async,
// fused +bias / LN / ReLU epilogue.
// ---------------------------------------------------------------------------
#define KC     64
#define A_LDH  72
#define B_LDH  136
#define A_STGB (128 * A_LDH * 2)            // 18432 B
#define B_STGB (KC * B_LDH * 2)             // 17408 B
#define OFF_B  (3 * A_STGB)                 // 55296
#define OFF_ST (OFF_B + 3 * B_STGB)         // 107520
#define AGG_SMEM (OFF_ST + 1024)            // 108544 B

__device__ __forceinline__ void agg_load_stage(char* smem, int stg,
                                               const __half* __restrict__ adjb,
                                               const __half* __restrict__ pb,
                                               int k0, int tid)
{
    char* sA = smem + stg * A_STGB;
    char* sB = smem + OFF_B + stg * B_STGB;
    #pragma unroll
    for (int it = 0; it < 4; ++it) {
        int i = tid + it * 256;
        int r = i >> 3, c = i & 7;
        cp_async16(sA + (r * A_LDH + c * 8) * 2,
                   adjb + (size_t)r * N_SZ + k0 + c * 8);
    }
    #pragma unroll
    for (int it = 0; it < 4; ++it) {
        int i = tid + it * 256;
        int r = i >> 4, c = i & 15;
        cp_async16(sB + (r * B_LDH + c * 8) * 2,
                   pb + (size_t)(k0 + r) * HID + c * 8);
    }
    cp_commit();
}

template<typename OutT>
__global__ __launch_bounds__(256, 2) void agg_half(const __half* __restrict__ adjh,
                                                   const __half* __restrict__ p,
                                                   const float* __restrict__ bias,
                                                   const float* __restrict__ gamma,
                                                   const float* __restrict__ beta,
                                                   OutT* __restrict__ out)
{
    extern __shared__ char smem[];
    float* sC  = (float*)smem;
    float* sMu = (float*)(smem + OFF_ST);
    float* sRs = sMu + 128;

    const int tid  = threadIdx.x;
    const int warp = tid >> 5;
    const int wr   = warp >> 1;
    const int wc   = warp & 1;
    const int b    = blockIdx.y;
    const int n0   = blockIdx.x * 128;

    const __half* adjb = adjh + ((size_t)b * N_SZ + n0) * N_SZ;
    const __half* pb   = p + (size_t)b * N_SZ * HID;

    wmma::fragment<wmma::accumulator, 16, 16, 16, float> acc[2][4];
    #pragma unroll
    for (int i = 0; i < 2; i++)
        #pragma unroll
        for (int j = 0; j < 4; j++) wmma::fill_fragment(acc[i][j], 0.f);

    agg_load_stage(smem, 0, adjb, pb, 0, tid);
    agg_load_stage(smem, 1, adjb, pb, KC, tid);

    const int NT = N_SZ / KC;   // 32
    for (int kt = 0; kt < NT; ++kt) {
        cp_wait<1>();
        __syncthreads();

        int nk = kt + 2;
        if (nk < NT) agg_load_stage(smem, nk % 3, adjb, pb, nk * KC, tid);
        else         cp_commit();

        const int stg = kt % 3;
        const __half* sA = (const __half*)(smem + stg * A_STGB);
        const __half* sB = (const __half*)(smem + OFF_B + stg * B_STGB);

        #pragma unroll
        for (int ks = 0; ks < KC / 16; ++ks) {
            wmma::fragment<wmma::matrix_a, 16, 16, 16, __half, wmma::row_major> fa[2];
            wmma::fragment<wmma::matrix_b, 16, 16, 16, __half, wmma::row_major> fb[4];
            #pragma unroll
            for (int i = 0; i < 2; i++)
                wmma::load_matrix_sync(fa[i], sA + (wr * 32 + i * 16) * A_LDH + ks * 16, A_LDH);
            #pragma unroll
            for (int j = 0; j < 4; j++)
                wmma::load_matrix_sync(fb[j], sB + (ks * 16) * B_LDH + wc * 64 + j * 16, B_LDH);
            #pragma unroll
            for (int i = 0; i < 2; i++)
                #pragma unroll
                for (int j = 0; j < 4; j++)
                    wmma::mma_sync(acc[i][j], fa[i], fb[j], acc[i][j]);
        }
    }
    __syncthreads();

    #pragma unroll
    for (int i = 0; i < 2; i++)
        #pragma unroll
        for (int j = 0; j < 4; j++)
            wmma::store_matrix_sync(sC + (wr * 32 + i * 16) * SC_LD + wc * 64 + j * 16,
                                    acc[i][j], SC_LD, wmma::mem_row_major);
    __syncthreads();

    {
        int r = tid >> 1, half = tid & 1;
        const float* rp = sC + r * SC_LD + half * 64;
        const float* bp = bias + half * 64;
        float s = 0.f, s2 = 0.f;
        #pragma unroll 8
        for (int c = 0; c < 64; c++) {
            float v = rp[c] + __ldg(&bp[c]);
            s  += v;
            s2 += v * v;
        }
        s  += __shfl_xor_sync(0xFFFFFFFF, s, 1);
        s2 += __shfl_xor_sync(0xFFFFFFFF, s2, 1);
        if (half == 0) {
            float mu  = s * (1.f / 128.f);
            float var = s2 * (1.f / 128.f) - mu * mu;
            sMu[r] = mu;
            sRs[r] = rsqrtf(var + 1e-5f);
        }
    }
    __syncthreads();

    OutT* ob = out + ((size_t)b * N_SZ + n0) * HID;
    #pragma unroll
    for (int i = tid; i < 128 * 128; i += 256) {
        int r = i >> 7, c = i & 127;
        float v = sC[r * SC_LD + c] + __ldg(&bias[c]);
        v = (v - sMu[r]) * sRs[r] * __ldg(&gamma[c]) + __ldg(&beta[c]);
        v = fmaxf(v, 0.f);
        if constexpr (sizeof(OutT) == 2)
            ob[(size_t)r * HID + c] = __float2half_rn(v);
        else
            ob[(size_t)r * HID + c] = v;
    }
}

// ---------------------------------------------------------------------------
// agg_conv (layer 0): cp.async fp32 adj staging (3 stages, KC=32), single
// sync per iteration: convert(stage kt -> A16[kt%2], + STG.128 to g_adjh)
// overlaps MMA on A16[(kt-1)%2] x B[(kt-1)%4]. B has 4 stages to avoid the
// lagged-read race. Fused +bias / LN / ReLU epilogue.
// ---------------------------------------------------------------------------
#define CKC       32
#define CV_A32LD  36                          // floats per fp32 A row (32+4)
#define CV_A32B   (128 * CV_A32LD * 4)        // 18432 B
#define CV_A16LD  40                          // halfs per fp16 A row (32+8)
#define CV_A16B   (128 * CV_A16LD * 2)        // 10240 B
#define CV_OFF_A16 (3 * CV_A32B)              // 55296
#define CV_BSTG   (CKC * B_LDH * 2)           // 8704 B
#define CV_OFF_B  (CV_OFF_A16 + 2 * CV_A16B)  // 75776
#define CV_OFF_ST (CV_OFF_B + 4 * CV_BSTG)    // 110592
#define CONV_SMEM (CV_OFF_ST + 1024)          // 111616 B

__device__ __forceinline__ void conv_load_stage(char* smem, int a_stg, int b_stg,
                                                const float* __restrict__ adjb,
                                                const __half* __restrict__ pb,
                                                int k0, int tid)
{
    float* sA = (float*)(smem + a_stg * CV_A32B);
    char*  sB = smem + CV_OFF_B + b_stg * CV_BSTG;
    #pragma unroll
    for (int it = 0; it < 4; ++it) {          // 1024 chunks: 128 rows x 8 float4
        int i = tid + it * 256;
        int r = i >> 3, c = i & 7;
        cp_async16(sA + r * CV_A32LD + c * 4,
                   adjb + (size_t)r * N_SZ + k0 + c * 4);
    }
    #pragma unroll
    for (int it = 0; it < 2; ++it) {          // 512 chunks: 32 rows x 16
        int i = tid + it * 256;
        int r = i >> 4, c = i & 15;
        cp_async16(sB + (r * B_LDH + c * 8) * 2,
                   pb + (size_t)(k0 + r) * HID + c * 8);
    }
    cp_commit();
}

__global__ __launch_bounds__(256, 2) void agg_conv(const float* __restrict__ adj,
                                                   const __half* __restrict__ p,
                                                   const float* __restrict__ bias,
                                                   const float* __restrict__ gamma,
                                                   const float* __restrict__ beta,
                                                   __half* __restrict__ adjh_out,
                                                   __half* __restrict__ out)
{
    extern __shared__ char smem[];
    float* sC  = (float*)smem;                // epilogue overlay (67.5 KB < CV_OFF_B)
    float* sMu = (float*)(smem + CV_OFF_ST);
    float* sRs = sMu + 128;

    const int tid  = threadIdx.x;
    const int warp = tid >> 5;
    const int wr   = warp >> 1;
    const int wc   = warp & 1;
    const int b    = blockIdx.y;
    const int n0   = blockIdx.x * 128;

    const float*  adjb  = adj + ((size_t)b * N_SZ + n0) * N_SZ;
    __half*       adjhb = adjh_out + ((size_t)b * N_SZ + n0) * N_SZ;
    const __half* pb    = p + (size_t)b * N_SZ * HID;

    wmma::fragment<wmma::accumulator, 16, 16, 16, float> acc[2][4];
    #pragma unroll
    for (int i = 0; i < 2; i++)
        #pragma unroll
        for (int j = 0; j < 4; j++) wmma::fill_fragment(acc[i][j], 0.f);

    // prologue: two stages in flight
    conv_load_stage(smem, 0, 0, adjb, pb, 0, tid);
    conv_load_stage(smem, 1, 1, adjb, pb, CKC, tid);

    const int NT = N_SZ / CKC;   // 64
    for (int kt = 0; kt < NT; ++kt) {
        cp_wait<1>();
        __syncthreads();          // fp32 stage kt + B stage kt ready;
                                  // also: A16[(kt-1)%2] writes visible

        int nk = kt + 2;
        if (nk < NT) conv_load_stage(smem, nk % 3, nk % 4, adjb, pb, nk * CKC, tid);
        else         cp_commit();

        // convert fp32 stage kt -> A16[kt%2] (+ fp16 adjacency to gmem)
        {
            const float* a32 = (const float*)(smem + (kt % 3) * CV_A32B);
            __half* a16 = (__half*)(smem + CV_OFF_A16 + (kt & 1) * CV_A16B);
            const int k0 = kt * CKC;
            #pragma unroll
            for (int it = 0; it < 2; ++it) {   // 512 out-chunks of 16B
                int i = tid + it * 256;
                int r = i >> 2, j = i & 3;     // 128 rows x 4 groups of 8 floats
                float4 v0 = *(const float4*)(a32 + r * CV_A32LD + j * 8);
                float4 v1 = *(const float4*)(a32 + r * CV_A32LD + j * 8 + 4);
                union { __half2 h[4]; uint4 u; } pk;
                pk.h[0] = __floats2half2_rn(v0.x, v0.y);
                pk.h[1] = __floats2half2_rn(v0.z, v0.w);
                pk.h[2] = __floats2half2_rn(v1.x, v1.y);
                pk.h[3] = __floats2half2_rn(v1.z, v1.w);
                *(uint4*)(a16 + r * CV_A16LD + j * 8) = pk.u;
                *(uint4*)(adjhb + (size_t)r * N_SZ + k0 + j * 8) = pk.u;
            }
        }

        // MMA lags by one k-chunk: consumes A16[(kt-1)%2] x B[(kt-1)%4]
        if (kt > 0) {
            const __half* sA = (const __half*)(smem + CV_OFF_A16 + ((kt - 1) & 1) * CV_A16B);
            const __half* sB = (const __half*)(smem + CV_OFF_B + ((kt - 1) & 3) * CV_BSTG);
            #pragma unroll
            for (int ks = 0; ks < CKC / 16; ++ks) {
                wmma::fragment<wmma::matrix_a, 16, 16, 16, __half, wmma::row_major> fa[2];
                wmma::fragment<wmma::matrix_b, 16, 16, 16, __half, wmma::row_major> fb[4];
                #pragma unroll
                for (int i = 0; i < 2; i++)
                    wmma::load_matrix_sync(fa[i], sA + (wr * 32 + i * 16) * CV_A16LD + ks * 16, CV_A16LD);
                #pragma unroll
                for (int j = 0; j < 4; j++)
                    wmma::load_matrix_sync(fb[j], sB + (ks * 16) * B_LDH + wc * 64 + j * 16, B_LDH);
                #pragma unroll
                for (int i = 0; i < 2; i++)
                    #pragma unroll
                    for (int j = 0; j < 4; j++)
                        wmma::mma_sync(acc[i][j], fa[i], fb[j], acc[i][j]);
            }
        }
    }

    // tail: final k-chunk's MMA (A16[(NT-1)%2] x B[(NT-1)%4])
    __syncthreads();   // last convert visible to all warps
    {
        const __half* sA = (const __half*)(smem + CV_OFF_A16 + ((NT - 1) & 1) * CV_A16B);
        const __half* sB = (const __half*)(smem + CV_OFF_B + ((NT - 1) & 3) * CV_BSTG);
        #pragma unroll
        for (int ks = 0; ks < CKC / 16; ++ks) {
            wmma::fragment<wmma::matrix_a, 16, 16, 16, __half, wmma::row_major> fa[2];
            wmma::fragment<wmma::matrix_b, 16, 16, 16, __half, wmma::row_major> fb[4];
            #pragma unroll
            for (int i = 0; i < 2; i++)
                wmma::load_matrix_sync(fa[i], sA + (wr * 32 + i * 16) * CV_A16LD + ks * 16, CV_A16LD);
            #pragma unroll
            for (int j = 0; j < 4; j++)
                wmma::load_matrix_sync(fb[j], sB + (ks * 16) * B_LDH + wc * 64 + j * 16, B_LDH);
            #pragma unroll
            for (int i = 0; i < 2; i++)
                #pragma unroll
                for (int j = 0; j < 4; j++)
                    wmma::mma_sync(acc[i][j], fa[i], fb[j], acc[i][j]);
        }
    }
    __syncthreads();   // all LDSM reads done before sC overlays smem

    #pragma unroll
    for (int i = 0; i < 2; i++)
        #pragma unroll
        for (int j = 0; j < 4; j++)
            wmma::store_matrix_sync(sC + (wr * 32 + i * 16) * SC_LD + wc * 64 + j * 16,
                                    acc[i][j], SC_LD, wmma::mem_row_major);
    __syncthreads();

    {
        int r = tid >> 1, half = tid & 1;
        const float* rp = sC + r * SC_LD + half * 64;
        const float* bp = bias + half * 64;
        float s = 0.f, s2 = 0.f;
        #pragma unroll 8
        for (int c = 0; c < 64; c++) {
            float v = rp[c] + __ldg(&bp[c]);
            s  += v;
            s2 += v * v;
        }
        s  += __shfl_xor_sync(0xFFFFFFFF, s, 1);
        s2 += __shfl_xor_sync(0xFFFFFFFF, s2, 1);
        if (half == 0) {
            float mu  = s * (1.f / 128.f);
            float var = s2 * (1.f / 128.f) - mu * mu;
            sMu[r] = mu;
            sRs[r] = rsqrtf(var + 1e-5f);
        }
    }
    __syncthreads();

    __half* ob = out + ((size_t)b * N_SZ + n0) * HID;
    #pragma unroll
    for (int i = tid; i < 128 * 128; i += 256) {
        int r = i >> 7, c = i & 127;
        float v = sC[r * SC_LD + c] + __ldg(&bias[c]);
        v = (v - sMu[r]) * sRs[r] * __ldg(&gamma[c]) + __ldg(&beta[c]);
        ob[(size_t)r * HID + c] = __float2half_rn(fmaxf(v, 0.f));
    }
}

// ---------------------------------------------------------------------------
extern "C" void kernel_launch(void* const* d_in, const int* in_sizes, int n_in,
                              void* d_out, int out_size)
{
    const float* x   = (const float*)d_in[0];
    const float* adj = (const float*)d_in[1];
    const float* W[3]  = {(const float*)d_in[2],  (const float*)d_in[6],  (const float*)d_in[10]};
    const float* bb[3] = {(const float*)d_in[3],  (const float*)d_in[7],  (const float*)d_in[11]};
    const float* gg[3] = {(const float*)d_in[4],  (const float*)d_in[8],  (const float*)d_in[12]};
    const float* be[3] = {(const float*)d_in[5],  (const float*)d_in[9],  (const float*)d_in[13]};
    float* out = (float*)d_out;

    cudaFuncSetAttribute(pw_half, cudaFuncAttributeMaxDynamicSharedMemorySize, PW_SMEM);
    cudaFuncSetAttribute(agg_half<__half>, cudaFuncAttributeMaxDynamicSharedMemorySize, AGG_SMEM);
    cudaFuncSetAttribute(agg_half<float>,  cudaFuncAttributeMaxDynamicSharedMemorySize, AGG_SMEM);
    cudaFuncSetAttribute(agg_conv, cudaFuncAttributeMaxDynamicSharedMemorySize, CONV_SMEM);

    __half *adjh, *xh, *pp, *hh, *wh;
    cudaGetSymbolAddress((void**)&adjh, g_adjh);
    cudaGetSymbolAddress((void**)&xh,   g_xh);
    cudaGetSymbolAddress((void**)&pp,   g_p);
    cudaGetSymbolAddress((void**)&hh,   g_hh);
    cudaGetSymbolAddress((void**)&wh,   g_wh);

    conv_fp16<<<1024, 256>>>((const float4*)x, (__half2*)xh, (B_SZ * N_SZ * HID) / 4);
    conv_w<<<192, 256>>>(W[0], W[1], W[2], wh);

    dim3 aggGrid(N_SZ / 128, B_SZ);   // (16, 16)

    // layer 0: projection then fused convert+agg (also emits fp16 adjacency)
    pw_half<<<(B_SZ * N_SZ) / 128, 256, PW_SMEM>>>(xh, wh, pp);
    agg_conv<<<aggGrid, 256, CONV_SMEM>>>(adj, pp, bb[0], gg[0], be[0], adjh, hh);
    // layer 1
    pw_half<<<(B_SZ * N_SZ) / 128, 256, PW_SMEM>>>(hh, wh + 1 * HID * HID, pp);
    agg_half<__half><<<aggGrid, 256, AGG_SMEM>>>(adjh, pp, bb[1], gg[1], be[1], hh);
    // layer 2
    pw_half<<<(B_SZ * N_SZ) / 128, 256, PW_SMEM>>>(hh, wh + 2 * HID * HID, pp);
    agg_half<float><<<aggGrid, 256, AGG_SMEM>>>(adjh, pp, bb[2], gg[2], be[2], out);
}